// round 10
// baseline (speedup 1.0000x reference)
#include <cuda_runtime.h>
#include <cstdint>

// QuantizedEmbedding R10: full-TMA path (R9) +
//  - 3-deep input buffers, bulk reads issued 2 tokens ahead
//  - L2 evict_first policy on the output bulk stores (write stream is never
//    re-read; stop it evicting gathered weight rows from L2)

static constexpr int PACKED   = 2048;    // packed int32 per row (8KB)
static constexpr int NGROUPS  = 128;
static constexpr int DIM      = 4096;
static constexpr int THREADS  = 256;
static constexpr int WARPS    = THREADS / 32;          // 8
static constexpr int TOKS     = 4;                      // tokens per CTA
static constexpr int NBI      = 3;                      // input buffers per warp
static constexpr int IN_P     = PACKED / WARPS;         // 256 int32 = 1KB
static constexpr int IN_B     = IN_P * 4;               // 1024 B
static constexpr int SLICE_F  = DIM / WARPS;            // 512 floats
static constexpr int SLICE_B  = SLICE_F * 4;            // 2048 B
static constexpr int SMEM_IN    = 0;                                  // 8*3*1KB = 24KB
static constexpr int SMEM_OUT   = WARPS * NBI * IN_B;                 // 24576
static constexpr int SMEM_MBAR  = SMEM_OUT + WARPS * 2 * SLICE_B;     // 57344
static constexpr int SMEM_BYTES = SMEM_MBAR + WARPS * NBI * 8 + 64;   // ~57.6KB

__device__ __forceinline__ float4 dq2(int a, int b, float s) {
    float4 r;
    r.x = (float)(a / 16 - 8) * s;       // trunc-toward-zero high nibble
    r.y = (float)((a & 15) - 8) * s;     // nonneg mod-16 low nibble
    r.z = (float)(b / 16 - 8) * s;
    r.w = (float)((b & 15) - 8) * s;
    return r;
}

__device__ __forceinline__ void mbar_wait(uint32_t mbar, uint32_t parity) {
    asm volatile(
        "{\n\t"
        ".reg .pred P;\n\t"
        "WL_%=:\n\t"
        "mbarrier.try_wait.parity.acquire.cta.shared::cta.b64 P, [%0], %1, 0x989680;\n\t"
        "@P bra.uni WD_%=;\n\t"
        "bra.uni WL_%=;\n\t"
        "WD_%=:\n\t"
        "}"
        :: "r"(mbar), "r"(parity) : "memory");
}

__device__ __forceinline__ void issue_read(uint32_t dst, const int* src, uint32_t mbar) {
    asm volatile("mbarrier.arrive.expect_tx.shared.b64 _, [%0], %1;"
                 :: "r"(mbar), "n"(IN_B) : "memory");
    asm volatile("cp.async.bulk.shared::cta.global.mbarrier::complete_tx::bytes "
                 "[%0], [%1], %2, [%3];"
                 :: "r"(dst), "l"(src), "n"(IN_B), "r"(mbar) : "memory");
}

__global__ void __launch_bounds__(THREADS)
qemb_kernel(const int* __restrict__ indices,
            const int* __restrict__ weight,
            const float* __restrict__ scales,
            float* __restrict__ out,
            int n_tokens)
{
    extern __shared__ __align__(128) unsigned char smem[];
    uint32_t sbase = (uint32_t)__cvta_generic_to_shared(smem);

    int t    = threadIdx.x;
    int warp = t >> 5;
    int lane = t & 31;
    long base = (long)blockIdx.x * TOKS;   // 16384 = 4096*4, exact

    uint32_t in0  = sbase + SMEM_IN  + warp * NBI * IN_B;     // [3][1KB]
    uint32_t out0 = sbase + SMEM_OUT + warp * 2 * SLICE_B;    // [2][2KB]
    uint32_t mb0  = sbase + SMEM_MBAR + warp * NBI * 8;       // 3 mbarriers

    if (lane == 0) {
        #pragma unroll
        for (int j = 0; j < NBI; j++)
            asm volatile("mbarrier.init.shared.b64 [%0], 1;" :: "r"(mb0 + j * 8) : "memory");
        asm volatile("fence.proxy.async.shared::cta;" ::: "memory");
    }
    __syncwarp();

    // evict_first policy for the write stream
    uint64_t pol;
    asm("createpolicy.fractional.L2::evict_first.b64 %0, 1.0;" : "=l"(pol));

    int4 idx4 = __ldg(reinterpret_cast<const int4*>(indices + base));
    int idxs[TOKS] = { idx4.x, idx4.y, idx4.z, idx4.w };

    int goff = warp * 16 + (lane >> 1);   // scale group for this thread

    // prologue: issue reads for tokens 0 and 1; prefetch scale 0
    if (lane == 0) {
        issue_read(in0,        weight + (long)idxs[0] * PACKED + warp * IN_P, mb0);
        issue_read(in0 + IN_B, weight + (long)idxs[1] * PACKED + warp * IN_P, mb0 + 8);
    }
    float s = __ldg(scales + (long)idxs[0] * NGROUPS + goff);

    #pragma unroll
    for (int i = 0; i < TOKS; i++) {
        int kin  = i % NBI;
        int kout = i & 1;

        // issue read for token i+2 (buffer consumed at iter i-1)
        if (i + 2 < TOKS && lane == 0) {
            int kn = (i + 2) % NBI;
            issue_read(in0 + kn * IN_B,
                       weight + (long)idxs[i + 2] * PACKED + warp * IN_P,
                       mb0 + kn * 8);
        }
        // prefetch next scale
        float ns = s;
        if (i + 1 < TOKS)
            ns = __ldg(scales + (long)idxs[i + 1] * NGROUPS + goff);

        // wait for token i's slice; buffer kin's phase flips every NBI uses
        mbar_wait(mb0 + kin * 8, (i / NBI) & 1);

        uint32_t a0 = in0 + kin * IN_B + lane * 32;
        int4 w0, w1;
        asm volatile("ld.shared.v4.u32 {%0,%1,%2,%3}, [%4];"
                     : "=r"(w0.x), "=r"(w0.y), "=r"(w0.z), "=r"(w0.w) : "r"(a0));
        asm volatile("ld.shared.v4.u32 {%0,%1,%2,%3}, [%4];"
                     : "=r"(w1.x), "=r"(w1.y), "=r"(w1.z), "=r"(w1.w) : "r"(a0 + 16));

        // out buffer kout reuse guard (its store committed at iter i-2)
        if (i >= 2 && lane == 0)
            asm volatile("cp.async.bulk.wait_group %0;" :: "n"(1) : "memory");
        __syncwarp();

        float4* bp = reinterpret_cast<float4*>(smem + SMEM_OUT
                       + warp * 2 * SLICE_B + kout * SLICE_B) + lane * 4;
        bp[0] = dq2(w0.x, w0.y, s);
        bp[1] = dq2(w0.z, w0.w, s);
        bp[2] = dq2(w1.x, w1.y, s);
        bp[3] = dq2(w1.z, w1.w, s);

        asm volatile("fence.proxy.async.shared::cta;" ::: "memory");
        __syncwarp();

        if (lane == 0) {
            void* g = (void*)(out + (base + i) * DIM + warp * SLICE_F);
            asm volatile("cp.async.bulk.global.shared::cta.bulk_group.L2::cache_hint "
                         "[%0], [%1], %2, %3;"
                         :: "l"(g), "r"(out0 + kout * SLICE_B), "n"(SLICE_B), "l"(pol)
                         : "memory");
            asm volatile("cp.async.bulk.commit_group;" ::: "memory");
        }

        s = ns;
    }

    if (lane == 0)
        asm volatile("cp.async.bulk.wait_group 0;" ::: "memory");
}

extern "C" void kernel_launch(void* const* d_in, const int* in_sizes, int n_in,
                              void* d_out, int out_size)
{
    const int*   indices = (const int*)d_in[0];
    const int*   weight  = (const int*)d_in[1];
    const float* scales  = (const float*)d_in[2];
    float*       out     = (float*)d_out;

    int n_tokens = in_sizes[0];  // 16384

    cudaFuncSetAttribute(qemb_kernel,
                         cudaFuncAttributeMaxDynamicSharedMemorySize, SMEM_BYTES);
    cudaFuncSetAttribute(qemb_kernel,
                         cudaFuncAttributePreferredSharedMemoryCarveout, 100);

    int grid = n_tokens / TOKS;  // 4096
    qemb_kernel<<<grid, THREADS, SMEM_BYTES>>>(indices, weight, scales, out, n_tokens);
}

// round 11
// speedup vs baseline: 1.0235x; 1.0235x over previous
#include <cuda_runtime.h>
#include <cstdint>

// QuantizedEmbedding R11: consolidated full-TMA warp-autonomous pipeline (R9)
//  - all 4 token scales prefetched in prologue (no per-iter scale LDG chain)
//  - store-drain wait_group moved BEFORE read mbar_wait (waits overlap)
//  - 2 input + 2 output buffers per warp (49KB smem), no cache-policy games

static constexpr int PACKED   = 2048;    // packed int32 per row (8KB)
static constexpr int NGROUPS  = 128;
static constexpr int DIM      = 4096;
static constexpr int THREADS  = 256;
static constexpr int WARPS    = THREADS / 32;          // 8
static constexpr int TOKS     = 4;                      // tokens per CTA
static constexpr int IN_P     = PACKED / WARPS;         // 256 int32 = 1KB per warp slice
static constexpr int IN_B     = IN_P * 4;               // 1024 B
static constexpr int SLICE_F  = DIM / WARPS;            // 512 floats = 2KB out slice
static constexpr int SLICE_B  = SLICE_F * 4;            // 2048 B
static constexpr int SMEM_IN    = 0;                               // 8*2*1KB = 16KB
static constexpr int SMEM_OUT   = WARPS * 2 * IN_B;                // 16384
static constexpr int SMEM_MBAR  = SMEM_OUT + WARPS * 2 * SLICE_B;  // 49152
static constexpr int SMEM_BYTES = SMEM_MBAR + WARPS * 2 * 8 + 64;

__device__ __forceinline__ float4 dq2(int a, int b, float s) {
    float4 r;
    r.x = (float)(a / 16 - 8) * s;       // trunc-toward-zero high nibble
    r.y = (float)((a & 15) - 8) * s;     // nonneg mod-16 low nibble
    r.z = (float)(b / 16 - 8) * s;
    r.w = (float)((b & 15) - 8) * s;
    return r;
}

__device__ __forceinline__ void mbar_wait(uint32_t mbar, uint32_t parity) {
    asm volatile(
        "{\n\t"
        ".reg .pred P;\n\t"
        "WL_%=:\n\t"
        "mbarrier.try_wait.parity.acquire.cta.shared::cta.b64 P, [%0], %1, 0x989680;\n\t"
        "@P bra.uni WD_%=;\n\t"
        "bra.uni WL_%=;\n\t"
        "WD_%=:\n\t"
        "}"
        :: "r"(mbar), "r"(parity) : "memory");
}

__device__ __forceinline__ void issue_read(uint32_t dst, const int* src, uint32_t mbar) {
    asm volatile("mbarrier.arrive.expect_tx.shared.b64 _, [%0], %1;"
                 :: "r"(mbar), "n"(IN_B) : "memory");
    asm volatile("cp.async.bulk.shared::cta.global.mbarrier::complete_tx::bytes "
                 "[%0], [%1], %2, [%3];"
                 :: "r"(dst), "l"(src), "n"(IN_B), "r"(mbar) : "memory");
}

__global__ void __launch_bounds__(THREADS)
qemb_kernel(const int* __restrict__ indices,
            const int* __restrict__ weight,
            const float* __restrict__ scales,
            float* __restrict__ out,
            int n_tokens)
{
    extern __shared__ __align__(128) unsigned char smem[];
    uint32_t sbase = (uint32_t)__cvta_generic_to_shared(smem);

    int t    = threadIdx.x;
    int warp = t >> 5;
    int lane = t & 31;
    long base = (long)blockIdx.x * TOKS;   // 16384 = 4096*4, exact

    uint32_t in0  = sbase + SMEM_IN  + warp * 2 * IN_B;      // [2][1KB]
    uint32_t out0 = sbase + SMEM_OUT + warp * 2 * SLICE_B;   // [2][2KB]
    uint32_t mb0  = sbase + SMEM_MBAR + warp * 16;           // 2 mbarriers

    if (lane == 0) {
        asm volatile("mbarrier.init.shared.b64 [%0], 1;" :: "r"(mb0)     : "memory");
        asm volatile("mbarrier.init.shared.b64 [%0], 1;" :: "r"(mb0 + 8) : "memory");
        asm volatile("fence.proxy.async.shared::cta;" ::: "memory");
    }
    __syncwarp();

    int4 idx4 = __ldg(reinterpret_cast<const int4*>(indices + base));
    int idxs[TOKS] = { idx4.x, idx4.y, idx4.z, idx4.w };

    int goff = warp * 16 + (lane >> 1);   // scale group for this thread

    // prologue: issue read of token 0; prefetch ALL 4 scales (independent)
    if (lane == 0)
        issue_read(in0, weight + (long)idxs[0] * PACKED + warp * IN_P, mb0);
    float sc[TOKS];
    #pragma unroll
    for (int j = 0; j < TOKS; j++)
        sc[j] = __ldg(scales + (long)idxs[j] * NGROUPS + goff);

    #pragma unroll
    for (int i = 0; i < TOKS; i++) {
        int k = i & 1;

        // issue read for token i+1 into the other buffer (consumed at i-1)
        if (i + 1 < TOKS && lane == 0) {
            uint32_t kn = (i + 1) & 1;
            issue_read(in0 + kn * IN_B,
                       weight + (long)idxs[i + 1] * PACKED + warp * IN_P,
                       mb0 + kn * 8);
        }

        // out-buffer k drain guard FIRST (overlaps with the read wait below)
        if (i >= 2 && lane == 0)
            asm volatile("cp.async.bulk.wait_group %0;" :: "n"(1) : "memory");

        // wait for token i's input slice: parity flips every 2 uses
        mbar_wait(mb0 + k * 8, (i >> 1) & 1);

        uint32_t a0 = in0 + k * IN_B + lane * 32;
        int4 w0, w1;
        asm volatile("ld.shared.v4.u32 {%0,%1,%2,%3}, [%4];"
                     : "=r"(w0.x), "=r"(w0.y), "=r"(w0.z), "=r"(w0.w) : "r"(a0));
        asm volatile("ld.shared.v4.u32 {%0,%1,%2,%3}, [%4];"
                     : "=r"(w1.x), "=r"(w1.y), "=r"(w1.z), "=r"(w1.w) : "r"(a0 + 16));
        __syncwarp();   // all lanes past wait_group point before STS into buffer k

        float s = sc[i];
        float4* bp = reinterpret_cast<float4*>(smem + SMEM_OUT
                       + warp * 2 * SLICE_B + k * SLICE_B) + lane * 4;
        bp[0] = dq2(w0.x, w0.y, s);
        bp[1] = dq2(w0.z, w0.w, s);
        bp[2] = dq2(w1.x, w1.y, s);
        bp[3] = dq2(w1.z, w1.w, s);

        asm volatile("fence.proxy.async.shared::cta;" ::: "memory");
        __syncwarp();

        if (lane == 0) {
            void* g = (void*)(out + (base + i) * DIM + warp * SLICE_F);
            asm volatile("cp.async.bulk.global.shared::cta.bulk_group [%0], [%1], %2;"
                         :: "l"(g), "r"(out0 + k * SLICE_B), "n"(SLICE_B) : "memory");
            asm volatile("cp.async.bulk.commit_group;" ::: "memory");
        }
    }

    if (lane == 0)
        asm volatile("cp.async.bulk.wait_group 0;" ::: "memory");
}

extern "C" void kernel_launch(void* const* d_in, const int* in_sizes, int n_in,
                              void* d_out, int out_size)
{
    const int*   indices = (const int*)d_in[0];
    const int*   weight  = (const int*)d_in[1];
    const float* scales  = (const float*)d_in[2];
    float*       out     = (float*)d_out;

    int n_tokens = in_sizes[0];  // 16384

    cudaFuncSetAttribute(qemb_kernel,
                         cudaFuncAttributeMaxDynamicSharedMemorySize, SMEM_BYTES);
    cudaFuncSetAttribute(qemb_kernel,
                         cudaFuncAttributePreferredSharedMemoryCarveout, 100);

    int grid = n_tokens / TOKS;  // 4096
    qemb_kernel<<<grid, THREADS, SMEM_BYTES>>>(indices, weight, scales, out, n_tokens);
}